// round 1
// baseline (speedup 1.0000x reference)
#include <cuda_runtime.h>

// SplineActivation: y[b,w] = clamped cubic B-spline (16 uniform knots on [-3,3],
// degree 3) of x[b,w] with per-channel coefficients coefs[w, 0..17].
//
// Strategy: the spline restricted to knot interval k is a cubic polynomial per
// (channel, interval). Precompute all 1024*15 cubics once (FP64, exact fit via
// divided differences of the reference Cox-de Boor evaluated at 4 nodes), then
// the hot kernel is: interval index -> one LDS.128 -> 3-FMA Horner. Memory-bound.

#define NB_INTERVALS 15
#define W_TOTAL      1024
#define B_TOTAL      8192
#define CH_TILE      256
#define COEF_N       18

// 240 KB static device scratch (allowed; no allocation APIs used).
// Layout [interval][channel] so the per-block smem stage is coalesced.
__device__ float4 g_poly[NB_INTERVALS * W_TOTAL];

// ---------------------------------------------------------------------------
// Precompute: exact per-(channel, interval) cubic in s = x - knot[k].
// Replicates the reference Cox-de Boor in double (knots are the float32 casts
// of numpy linspace values, promoted to double), samples 4 points per interval,
// and recovers monomial coefficients via Newton divided differences.
// ---------------------------------------------------------------------------
__global__ void build_poly_kernel(const float* __restrict__ coefs) {
    int idx = blockIdx.x * blockDim.x + threadIdx.x;
    if (idx >= NB_INTERVALS * W_TOTAL) return;
    int w  = idx & (W_TOTAL - 1);
    int iv = idx >> 10;              // interval 0..14

    // Clamped knot vector t[0..21] (float32 knot values promoted to double)
    double t[22];
#pragma unroll
    for (int j = 0; j < 16; j++) {
        double kd = -3.0 + (double)j * (6.0 / 15.0);   // numpy linspace formula
        t[3 + j] = (double)(float)kd;                  // reference casts to f32
    }
    t[0] = t[1] = t[2] = t[3];
    t[19] = t[20] = t[21] = t[18];

    const int kg = iv + 3;           // global span index, in [3, 17]
    double c[4];
#pragma unroll
    for (int j = 0; j < 4; j++) c[j] = (double)coefs[w * COEF_N + iv + j];

    const double x0    = t[kg];
    const double hh    = t[kg + 1] - t[kg];
    const double delta = hh / 3.0;

    double f[4];
#pragma unroll
    for (int m = 0; m < 4; m++) {
        double x = x0 + delta * (double)m;
        double left[3], right[3];
#pragma unroll
        for (int i2 = 1; i2 <= 3; i2++) {
            left [i2 - 1] = x - t[kg + 1 - i2];
            right[i2 - 1] = t[kg + i2] - x;
        }
        double N[4];
        N[0] = 1.0;
#pragma unroll
        for (int j = 1; j <= 3; j++) {
            double saved = 0.0;
#pragma unroll
            for (int r = 0; r < j; r++) {
                double temp = N[r] / (right[r] + left[j - 1 - r]);
                N[r] = saved + right[r] * temp;
                saved = left[j - 1 - r] * temp;
            }
            N[j] = saved;
        }
        f[m] = N[0] * c[0] + N[1] * c[1] + N[2] * c[2] + N[3] * c[3];
    }

    // Newton divided differences (equally spaced) -> monomial coeffs in s.
    double d1 = (f[1] - f[0]) / delta;
    double d2 = (f[2] - 2.0 * f[1] + f[0]) / (2.0 * delta * delta);
    double d3 = (f[3] - 3.0 * f[2] + 3.0 * f[1] - f[0]) / (6.0 * delta * delta * delta);
    double a0 = f[0];
    double a1 = d1 - delta * d2 + 2.0 * delta * delta * d3;
    double a2 = d2 - 3.0 * delta * d3;
    double a3 = d3;

    g_poly[iv * W_TOTAL + w] = make_float4((float)a0, (float)a1, (float)a2, (float)a3);
}

// ---------------------------------------------------------------------------
// Hot kernel: 256 threads = 256 channels per block; poly tile staged in smem.
// smem index sp[k*CH_TILE + t]: k-stride = 4096 B (multiple of 128 B) so each
// 8-lane LDS.128 phase spans words 0..31 -> conflict-free for any per-lane k.
// Grid = (4 col tiles) x 111 = 444 CTAs = exactly 3 per SM, single wave;
// rows handled grid-stride in 4-row chunks (4 independent LDGs for MLP).
// ---------------------------------------------------------------------------
__global__ __launch_bounds__(CH_TILE, 3)
void spline_eval_kernel(const float* __restrict__ X, float* __restrict__ Y) {
    extern __shared__ float4 sp[];   // [NB_INTERVALS][CH_TILE]
    const int t  = threadIdx.x;
    const int c0 = blockIdx.x * CH_TILE;

#pragma unroll
    for (int k = 0; k < NB_INTERVALS; k++)
        sp[k * CH_TILE + t] = g_poly[k * W_TOTAL + c0 + t];
    __syncthreads();

    const int col   = c0 + t;
    const int rstep = gridDim.y * 4;

    for (int r0 = blockIdx.y * 4; r0 < B_TOTAL; r0 += rstep) {
        const float* xp = X + (size_t)r0 * W_TOTAL + col;
        float*       yp = Y + (size_t)r0 * W_TOTAL + col;

        float xv[4];
#pragma unroll
        for (int q = 0; q < 4; q++) xv[q] = xp[q * W_TOTAL];

        float rv[4];
#pragma unroll
        for (int q = 0; q < 4; q++) {
            float x  = xv[q];
            float u  = fmaf(x, 2.5f, 7.5f);      // (x + 3) / 0.4
            float fi = floorf(u);
            fi       = fminf(fmaxf(fi, 0.0f), 14.0f);
            int   k  = (int)fi;
            float s  = x - fmaf(fi, 0.4f, -3.0f); // x - knot[k]
            float4 p = sp[k * CH_TILE + t];
            rv[q] = fmaf(fmaf(fmaf(p.w, s, p.z), s, p.y), s, p.x);
        }
#pragma unroll
        for (int q = 0; q < 4; q++) yp[q * W_TOTAL] = rv[q];
    }
}

// ---------------------------------------------------------------------------
extern "C" void kernel_launch(void* const* d_in, const int* in_sizes, int n_in,
                              void* d_out, int out_size) {
    const float* X     = (const float*)d_in[0];
    const float* coefs = (const float*)d_in[1];
    // Defensive: identify tensors by size (X has 8M elements, coefs 18K).
    if (n_in >= 2 && in_sizes[0] < in_sizes[1]) {
        X     = (const float*)d_in[1];
        coefs = (const float*)d_in[0];
    }
    float* Y = (float*)d_out;

    // Tiny precompute: 15360 threads, FP64, runs before the hot kernel in-stream.
    build_poly_kernel<<<(NB_INTERVALS * W_TOTAL + 255) / 256, 256>>>(coefs);

    const int smem_bytes = NB_INTERVALS * CH_TILE * (int)sizeof(float4); // 61440
    cudaFuncSetAttribute(spline_eval_kernel,
                         cudaFuncAttributeMaxDynamicSharedMemorySize, smem_bytes);

    dim3 grid(W_TOTAL / CH_TILE, 111);   // 4 x 111 = 444 = 3 * 148 CTAs
    spline_eval_kernel<<<grid, CH_TILE, smem_bytes>>>(X, Y);
}